// round 8
// baseline (speedup 1.0000x reference)
#include <cuda_runtime.h>
#include <cuda_fp16.h>
#include <cstdint>
#include <math.h>

#define NT      4096       // B*S tokens
#define DMODEL  2048
#define S_LEN   2048
#define BATCH   2
#define HQN     16
#define HKVN    8
#define HD      128
#define NEXP    8
#define FDIM    4096
#define NASSIGN (NT*2)
#define QKVN    4096       // 2048 q + 1024 k + 1024 v

typedef __half fp16;

// ---------------- scratch ----------------
__device__ float g_qkv [NT*QKVN];
__device__ float g_inter[NT*DMODEL];
__device__ float g_hbuf[NT*DMODEL];
__device__ float g_eout[NASSIGN*DMODEL];
__device__ int   g_perm[NASSIGN];
__device__ int   g_slot[NASSIGN];
__device__ int   g_tope[NASSIGN];
__device__ float g_wgt [NASSIGN];
__device__ int   g_cnt [NEXP];
__device__ int   g_off [NEXP];

// fp16 activation planes (single plane)
__device__ fp16 g_lnx [NT*DMODEL];
__device__ fp16 g_ctx [NT*DMODEL];
__device__ fp16 g_hh  [NT*DMODEL];
__device__ fp16 g_act [NASSIGN*FDIM];
// fp16 weights
__device__ fp16 g_qkvw[DMODEL*QKVN];
__device__ fp16 g_wo  [DMODEL*DMODEL];
__device__ fp16 g_w01 [(size_t)NEXP*DMODEL*2*FDIM];   // interleaved wi0/wi1
__device__ fp16 g_wom [(size_t)NEXP*FDIM*DMODEL];
// attention operands
__device__ fp16 g_qh[NT*HQN*HD];
__device__ fp16 g_kh[NT*HKVN*HD];
__device__ fp16 g_vh[NT*HKVN*HD];

__device__ __forceinline__ uint32_t packh2(fp16 a, fp16 b) {
    __half2 p; p.x = a; p.y = b;
    return *(uint32_t*)&p;
}
__device__ __forceinline__ void cp16(uint32_t dst, const void* src) {
    asm volatile("cp.async.cg.shared.global [%0], [%1], 16;" :: "r"(dst), "l"(src));
}
__device__ __forceinline__ void cp16_zero(uint32_t dst, const void* src) {
    asm volatile("cp.async.cg.shared.global [%0], [%1], 16, 0;" :: "r"(dst), "l"(src));
}
#define CP_COMMIT() asm volatile("cp.async.commit_group;" ::: "memory")

__device__ __forceinline__ void ldm_x4(uint32_t* r, uint32_t addr) {
    asm volatile("ldmatrix.sync.aligned.m8n8.x4.shared.b16 {%0,%1,%2,%3}, [%4];"
        : "=r"(r[0]), "=r"(r[1]), "=r"(r[2]), "=r"(r[3]) : "r"(addr));
}
__device__ __forceinline__ void ldm_x2t(uint32_t* r, uint32_t addr) {
    asm volatile("ldmatrix.sync.aligned.m8n8.x2.trans.shared.b16 {%0,%1}, [%2];"
        : "=r"(r[0]), "=r"(r[1]) : "r"(addr));
}
__device__ __forceinline__ void mma_f16(float* c, const uint32_t* a, const uint32_t* b) {
    asm volatile(
        "mma.sync.aligned.m16n8k16.row.col.f32.f16.f16.f32 "
        "{%0,%1,%2,%3}, {%4,%5,%6,%7}, {%8,%9}, {%0,%1,%2,%3};"
        : "+f"(c[0]), "+f"(c[1]), "+f"(c[2]), "+f"(c[3])
        : "r"(a[0]), "r"(a[1]), "r"(a[2]), "r"(a[3]), "r"(b[0]), "r"(b[1]));
}

// ---------------- vectorized weight convert (float4 -> 4 fp16) ----------------
// Converts flat row-major [K][ncol] into dst with row stride dstStride at colOff.
__global__ void wcvt4_k(const float* __restrict__ src, fp16* __restrict__ dst,
                        int ncol, int dstStride, int colOff,
                        long long srcZ, long long dstZ, long long total4)
{
    long long i = (long long)blockIdx.x * blockDim.x + threadIdx.x;
    if (i >= total4) return;
    int z = blockIdx.y;
    const float4* s = (const float4*)(src + (long long)z * srcZ);
    fp16* d = dst + (long long)z * dstZ;
    float4 v = s[i];
    long long e = i * 4;
    int kr = (int)(e / ncol);
    int n  = (int)(e % ncol);
    uint32_t* w = (uint32_t*)(d + (long long)kr * dstStride + colOff + n);
    w[0] = packh2(__float2half(v.x), __float2half(v.y));
    w[1] = packh2(__float2half(v.z), __float2half(v.w));
}

// ---------------- fused wi0/wi1 interleave convert ----------------
// dst col layout: [2n] = wi0[.][n], [2n+1] = wi1[.][n]; packed 16B writes.
__global__ void w01cvt_k(const float* __restrict__ wi0, const float* __restrict__ wi1,
                         fp16* __restrict__ dst, long long total4)
{
    long long i = (long long)blockIdx.x * blockDim.x + threadIdx.x;
    if (i >= total4) return;
    int z = blockIdx.y;
    const float4* s0 = (const float4*)(wi0 + (long long)z * DMODEL * FDIM);
    const float4* s1 = (const float4*)(wi1 + (long long)z * DMODEL * FDIM);
    float4 a = s0[i], b = s1[i];
    uint32_t* w = (uint32_t*)(dst + (long long)z * DMODEL * 2 * FDIM + i * 8);
    w[0] = packh2(__float2half(a.x), __float2half(b.x));
    w[1] = packh2(__float2half(a.y), __float2half(b.y));
    w[2] = packh2(__float2half(a.z), __float2half(b.z));
    w[3] = packh2(__float2half(a.w), __float2half(b.w));
}

// ---------------- RMSNorm (+optional fp32 out, fp16 out) ----------------
__global__ void rmsnorm_split_k(const float* __restrict__ x, const float* __restrict__ sc,
                                float* __restrict__ yf, fp16* __restrict__ yh)
{
    int row = blockIdx.x;
    int tid = threadIdx.x;
    const float* xr = x + (size_t)row * DMODEL;
    float ss = 0.f;
    for (int d = tid; d < DMODEL; d += 256) { float v = xr[d]; ss += v * v; }
    __shared__ float red[256];
    red[tid] = ss; __syncthreads();
    for (int st = 128; st > 0; st >>= 1) {
        if (tid < st) red[tid] += red[tid + st];
        __syncthreads();
    }
    float inv = rsqrtf(red[0] / (float)DMODEL + 1e-6f);
    size_t base = (size_t)row * DMODEL;
    for (int d = tid; d < DMODEL; d += 256) {
        float v = xr[d] * inv * sc[d];
        if (yf) yf[base + d] = v;
        yh[base + d] = __float2half(v);
    }
}

// ================= fp16 tensor-core GEMM =================
// BM=128, BN=256, BK=32; 8 warps (2x4), warp tile 64x64.
#define ASTR 40
#define BSTR 264
#define OFF_A(s) ((s)*5120)
#define OFF_B(s) (10240 + (s)*8448)
#define SMEM_GEMM_BYTES (27136*2)

__global__ __launch_bounds__(256, 1)
void fp16_gemm_k(const fp16* __restrict__ Ag, const fp16* __restrict__ Bg,
                 const float* __restrict__ res, float* __restrict__ Cf,
                 fp16* __restrict__ SH,
                 int M, int N, int K,
                 const int* __restrict__ perm,
                 const int* __restrict__ cnts, const int* __restrict__ offs,
                 long long strideB, int mode)
{
    extern __shared__ fp16 sm[];
    int rowBase = 0;
    const fp16* B = Bg;
    if (cnts) {
        int e = blockIdx.z;
        M = cnts[e];
        rowBase = offs[e];
        B = Bg + (long long)e * strideB;
    }
    int bm = blockIdx.y * 128;
    if (bm >= M) return;
    int bn = blockIdx.x * 256;

    int tid  = threadIdx.x;
    int lane = tid & 31;
    int w    = tid >> 5;
    int wm   = w & 1;          // 2 along M
    int wn   = w >> 1;         // 4 along N

    uint32_t smBase = (uint32_t)__cvta_generic_to_shared(sm);
    uint32_t aLane  = ((lane & 15) * ASTR + (lane >> 4) * 8) * 2;
    uint32_t bLane  = ((lane & 15) * BSTR) * 2;

    int rA  = tid >> 1;
    int ac0 = (tid & 1) * 16;
    int aIdx = -1;
    if (bm + rA < M) { int r = rowBase + bm + rA; aIdx = perm ? perm[r] : r; }

    int rB  = tid >> 3;            // 0..31
    int bc0 = (tid & 7) * 32;      // 0..224 (fp16 cols)

    float acc[4][8][4];
#pragma unroll
    for (int i = 0; i < 4; i++)
#pragma unroll
        for (int j = 0; j < 8; j++)
#pragma unroll
            for (int c = 0; c < 4; c++) acc[i][j][c] = 0.f;

    const int NKT = K >> 5;

    auto prefetch = [&](int kt, int st) {
        int k0 = kt << 5;
        uint32_t dA = smBase + (OFF_A(st) + rA * ASTR + ac0) * 2;
        if (aIdx >= 0) {
            const fp16* sa = Ag + (size_t)aIdx * K + k0 + ac0;
            cp16(dA, sa);      cp16(dA + 16, sa + 8);
        } else {
            cp16_zero(dA, Ag); cp16_zero(dA + 16, Ag);
        }
        uint32_t dB = smBase + (OFF_B(st) + rB * BSTR + bc0) * 2;
        const fp16* sb = B + (size_t)(k0 + rB) * N + bn + bc0;
#pragma unroll
        for (int j = 0; j < 4; j++) cp16(dB + j * 16, sb + j * 8);
    };

    prefetch(0, 0);
    CP_COMMIT();

    for (int kt = 0; kt < NKT; kt++) {
        int st = kt & 1;
        if (kt + 1 < NKT) {
            prefetch(kt + 1, st ^ 1);
            CP_COMMIT();
            asm volatile("cp.async.wait_group 1;" ::: "memory");
        } else {
            asm volatile("cp.async.wait_group 0;" ::: "memory");
        }
        __syncthreads();

        uint32_t aBase = smBase + (OFF_A(st) + wm * 64 * ASTR) * 2 + aLane;
        uint32_t bBase = smBase + (OFF_B(st)) * 2 + wn * 64 * 2 + bLane;

#pragma unroll
        for (int ks = 0; ks < 2; ks++) {
            uint32_t ah[4][4];
#pragma unroll
            for (int mf = 0; mf < 4; mf++) {
                uint32_t off = mf * (16 * ASTR * 2) + ks * 32;
                ldm_x4(ah[mf], aBase + off);
            }
            uint32_t bh[8][2];
#pragma unroll
            for (int nf = 0; nf < 8; nf++) {
                uint32_t off = nf * 16 + ks * (16 * BSTR * 2);
                ldm_x2t(bh[nf], bBase + off);
            }
#pragma unroll
            for (int mf = 0; mf < 4; mf++)
#pragma unroll
                for (int nf = 0; nf < 8; nf++)
                    mma_f16(acc[mf][nf], ah[mf], bh[nf]);
        }
        __syncthreads();
    }

    int g   = lane >> 2;
    int tig = lane & 3;
#pragma unroll
    for (int mf = 0; mf < 4; mf++) {
        int row0 = bm + wm * 64 + mf * 16 + g;
        int row1 = row0 + 8;
#pragma unroll
        for (int nf = 0; nf < 8; nf++) {
            int col = bn + wn * 64 + nf * 8 + tig * 2;
            if (mode == 0) {
                if (row0 < M) {
                    size_t o = (size_t)(rowBase + row0) * N + col;
                    float2 v = make_float2(acc[mf][nf][0], acc[mf][nf][1]);
                    if (res) { float2 r = *(const float2*)&res[o]; v.x += r.x; v.y += r.y; }
                    *(float2*)&Cf[o] = v;
                }
                if (row1 < M) {
                    size_t o = (size_t)(rowBase + row1) * N + col;
                    float2 v = make_float2(acc[mf][nf][2], acc[mf][nf][3]);
                    if (res) { float2 r = *(const float2*)&res[o]; v.x += r.x; v.y += r.y; }
                    *(float2*)&Cf[o] = v;
                }
            } else {
                // interleaved silu: even col = gate (wi0), odd col = value (wi1)
                int f = col >> 1;
                if (row0 < M) {
                    size_t o = (size_t)(rowBase + row0) * (size_t)(N >> 1) + f;
                    float a = acc[mf][nf][0], b = acc[mf][nf][1];
                    SH[o] = __float2half((a / (1.0f + __expf(-a))) * b);
                }
                if (row1 < M) {
                    size_t o = (size_t)(rowBase + row1) * (size_t)(N >> 1) + f;
                    float a = acc[mf][nf][2], b = acc[mf][nf][3];
                    SH[o] = __float2half((a / (1.0f + __expf(-a))) * b);
                }
            }
        }
    }
}

// ---------------- RoPE -> single fp16 plane ----------------
__global__ void rope1_k(const float* __restrict__ qkv, const int* __restrict__ pos,
                        int srcOff, int nheads, float scale,
                        fp16* __restrict__ outH, int total)
{
    int idx = blockIdx.x * blockDim.x + threadIdx.x;
    if (idx >= total) return;
    int i   = idx & 63;
    int th  = idx >> 6;
    int h   = th % nheads;
    int tok = th / nheads;
    float freq = powf(10000.0f, -(float)i / 64.0f);
    float ang = (float)pos[tok] * freq;
    float c = cosf(ang), s = sinf(ang);
    const float* row = qkv + (size_t)tok * QKVN + srcOff + h * HD;
    float x1 = row[i], x2 = row[i + 64];
    size_t o = (size_t)tok * (nheads * HD) + h * HD;
    outH[o + i]      = __float2half((x1 * c - x2 * s) * scale);
    outH[o + i + 64] = __float2half((x2 * c + x1 * s) * scale);
}

__global__ void splitv1_k(const float* __restrict__ qkv, fp16* __restrict__ vh, int total4)
{
    int idx = blockIdx.x * blockDim.x + threadIdx.x;
    if (idx >= total4) return;
    int e   = idx * 4;
    int tok = e >> 10;
    int d   = e & 1023;
    float4 v = *(const float4*)&qkv[(size_t)tok * QKVN + 3072 + d];
    uint32_t* w = (uint32_t*)&vh[e];
    w[0] = packh2(__float2half(v.x), __float2half(v.y));
    w[1] = packh2(__float2half(v.z), __float2half(v.w));
}

// ================= fp16 flash attention =================
// QT=64, KT=32, 4 warps; all single-plane fp16.
#define FQT 64
#define FKT 32
#define FSTR 136
#define F_Q 0
#define F_K(s) (8704 + (s)*4352)
#define F_V(s) (17408 + (s)*4352)
#define FLASH_SMEM_BYTES (26112*2)

__global__ __launch_bounds__(128)
void flash2_k(const fp16* __restrict__ Qh,
              const fp16* __restrict__ Kh, const fp16* __restrict__ Vh,
              const int* __restrict__ seg, fp16* __restrict__ Oh)
{
    extern __shared__ fp16 fsm[];
    __shared__ int Sq[FQT];
    __shared__ int Sk[2][FKT];

    int tid  = threadIdx.x;
    int lane = tid & 31;
    int w    = tid >> 5;
    int g    = lane >> 2;
    int tig  = lane & 3;

    int q0  = blockIdx.x * FQT;
    int h   = blockIdx.y;
    int b   = blockIdx.z;
    int tok0 = b * S_LEN;
    int hk  = h >> 1;

    uint32_t smBase = (uint32_t)__cvta_generic_to_shared(fsm);

    {
        int r  = tid >> 1;
        int c0 = (tid & 1) * 64;
        const fp16* sq = Qh + (size_t)(tok0 + q0 + r) * (HQN * HD) + h * HD + c0;
        uint32_t dq = smBase + (F_Q + r * FSTR + c0) * 2;
#pragma unroll
        for (int j = 0; j < 8; j++) cp16(dq + j * 16, sq + j * 8);
    }
    if (tid < FQT) Sq[tid] = seg[tok0 + q0 + tid];

    auto prefetch = [&](int kt, int st) {
        int k0 = kt * FKT;
        int r  = tid >> 2;
        int c0 = (tid & 3) * 32;
        size_t gbase = (size_t)(tok0 + k0 + r) * (HKVN * HD) + hk * HD + c0;
        uint32_t dk = smBase + (F_K(st) + r * FSTR + c0) * 2;
        uint32_t dv = smBase + (F_V(st) + r * FSTR + c0) * 2;
#pragma unroll
        for (int j = 0; j < 4; j++) {
            cp16(dk + j * 16, Kh + gbase + j * 8);
            cp16(dv + j * 16, Vh + gbase + j * 8);
        }
        if (tid < FKT) Sk[st][tid] = seg[tok0 + k0 + tid];
    };

    prefetch(0, 0);
    CP_COMMIT();

    float of[16][4];
#pragma unroll
    for (int nf = 0; nf < 16; nf++)
#pragma unroll
        for (int c = 0; c < 4; c++) of[nf][c] = 0.f;
    float m0 = -1e9f, m1 = -1e9f, l0 = 0.f, l1 = 0.f;

    uint32_t qAddr = smBase + (F_Q + (w * 16 + (lane & 15)) * FSTR + (lane >> 4) * 8) * 2;
    int ktokoff = (lane & 7) + ((lane >> 4) << 3);
    int kdhalf  = ((lane >> 3) & 1) * 8;
    int vrow    = lane & 15;

    int ktend = (q0 + FQT - 1) / FKT;
    int myrow0 = q0 + w * 16 + g;
    int myrow1 = myrow0 + 8;
    int sq0 = 0, sq1 = 0;

    for (int kt = 0; kt <= ktend; kt++) {
        int st = kt & 1;
        if (kt + 1 <= ktend) {
            prefetch(kt + 1, st ^ 1);
            CP_COMMIT();
            asm volatile("cp.async.wait_group 1;" ::: "memory");
        } else {
            asm volatile("cp.async.wait_group 0;" ::: "memory");
        }
        __syncthreads();
        if (kt == 0) { sq0 = Sq[w * 16 + g]; sq1 = Sq[w * 16 + g + 8]; }
        int k0 = kt * FKT;

        float sf[4][4];
#pragma unroll
        for (int nf = 0; nf < 4; nf++)
#pragma unroll
            for (int c = 0; c < 4; c++) sf[nf][c] = 0.f;

        uint32_t kBase = smBase + (F_K(st) + ktokoff * FSTR + kdhalf) * 2;

#pragma unroll
        for (int kk = 0; kk < 8; kk++) {
            uint32_t qh4[4];
            ldm_x4(qh4, qAddr + kk * 32);
#pragma unroll
            for (int p = 0; p < 2; p++) {
                uint32_t kh4[4];
                uint32_t off = (p * 16 * FSTR + kk * 16) * 2;
                ldm_x4(kh4, kBase + off);
                mma_f16(sf[2 * p],     qh4, kh4);
                mma_f16(sf[2 * p + 1], qh4, kh4 + 2);
            }
        }

#pragma unroll
        for (int nf = 0; nf < 4; nf++) {
            int c0g = k0 + nf * 8 + 2 * tig;
            int sk0 = Sk[st][nf * 8 + 2 * tig];
            int sk1 = Sk[st][nf * 8 + 2 * tig + 1];
            if (c0g > myrow0     || sk0 != sq0) sf[nf][0] = -1e9f;
            if (c0g + 1 > myrow0 || sk1 != sq0) sf[nf][1] = -1e9f;
            if (c0g > myrow1     || sk0 != sq1) sf[nf][2] = -1e9f;
            if (c0g + 1 > myrow1 || sk1 != sq1) sf[nf][3] = -1e9f;
        }
        float mx0 = -1e9f, mx1 = -1e9f;
#pragma unroll
        for (int nf = 0; nf < 4; nf++) {
            mx0 = fmaxf(mx0, fmaxf(sf[nf][0], sf[nf][1]));
            mx1 = fmaxf(mx1, fmaxf(sf[nf][2], sf[nf][3]));
        }
        mx0 = fmaxf(mx0, __shfl_xor_sync(0xffffffff, mx0, 1));
        mx0 = fmaxf(mx0, __shfl_xor_sync(0xffffffff, mx0, 2));
        mx1 = fmaxf(mx1, __shfl_xor_sync(0xffffffff, mx1, 1));
        mx1 = fmaxf(mx1, __shfl_xor_sync(0xffffffff, mx1, 2));
        float mn0 = fmaxf(m0, mx0), mn1 = fmaxf(m1, mx1);
        float al0 = __expf(m0 - mn0), al1 = __expf(m1 - mn1);
        m0 = mn0; m1 = mn1;
        float ls0 = 0.f, ls1 = 0.f;
#pragma unroll
        for (int nf = 0; nf < 4; nf++) {
            sf[nf][0] = __expf(sf[nf][0] - mn0);
            sf[nf][1] = __expf(sf[nf][1] - mn0);
            sf[nf][2] = __expf(sf[nf][2] - mn1);
            sf[nf][3] = __expf(sf[nf][3] - mn1);
            ls0 += sf[nf][0] + sf[nf][1];
            ls1 += sf[nf][2] + sf[nf][3];
        }
        l0 = l0 * al0 + ls0;
        l1 = l1 * al1 + ls1;
#pragma unroll
        for (int nf = 0; nf < 16; nf++) {
            of[nf][0] *= al0; of[nf][1] *= al0;
            of[nf][2] *= al1; of[nf][3] *= al1;
        }

        uint32_t vBase = smBase + (F_V(st) + vrow * FSTR) * 2;
#pragma unroll
        for (int t = 0; t < 2; t++) {
            uint32_t pah[4];
#pragma unroll
            for (int q = 0; q < 2; q++) {
                pah[2 * q]     = packh2(__float2half(sf[2 * t + q][0]),
                                        __float2half(sf[2 * t + q][1]));
                pah[2 * q + 1] = packh2(__float2half(sf[2 * t + q][2]),
                                        __float2half(sf[2 * t + q][3]));
            }
#pragma unroll
            for (int nf = 0; nf < 16; nf++) {
                uint32_t vh2[2];
                uint32_t off = (t * 16 * FSTR + nf * 8) * 2;
                ldm_x2t(vh2, vBase + off);
                mma_f16(of[nf], pah, vh2);
            }
        }
        __syncthreads();
    }

    l0 += __shfl_xor_sync(0xffffffff, l0, 1);
    l0 += __shfl_xor_sync(0xffffffff, l0, 2);
    l1 += __shfl_xor_sync(0xffffffff, l1, 1);
    l1 += __shfl_xor_sync(0xffffffff, l1, 2);
    float i0 = 1.0f / l0, i1 = 1.0f / l1;
    size_t r0 = (size_t)(tok0 + myrow0) * DMODEL + h * HD;
    size_t r1 = (size_t)(tok0 + myrow1) * DMODEL + h * HD;
#pragma unroll
    for (int nf = 0; nf < 16; nf++) {
        int col = nf * 8 + 2 * tig;
        *(uint32_t*)&Oh[r0 + col] = packh2(__float2half(of[nf][0] * i0),
                                           __float2half(of[nf][1] * i0));
        *(uint32_t*)&Oh[r1 + col] = packh2(__float2half(of[nf][2] * i1),
                                           __float2half(of[nf][3] * i1));
    }
}

// ---------------- gating ----------------
__global__ void gate_k(const float* __restrict__ h, const float* __restrict__ gw,
                       int* __restrict__ tope, float* __restrict__ wgt)
{
    int tok = blockIdx.x;
    int tid = threadIdx.x;
    float s[NEXP];
#pragma unroll
    for (int e = 0; e < NEXP; e++) s[e] = 0.f;
    const float* hr = h + (size_t)tok * DMODEL;
    for (int d = tid; d < DMODEL; d += 128) {
        float hv = hr[d];
#pragma unroll
        for (int e = 0; e < NEXP; e++) s[e] += hv * gw[d * NEXP + e];
    }
    __shared__ float red[NEXP][128];
#pragma unroll
    for (int e = 0; e < NEXP; e++) red[e][tid] = s[e];
    __syncthreads();
    for (int st = 64; st > 0; st >>= 1) {
        if (tid < st)
#pragma unroll
            for (int e = 0; e < NEXP; e++) red[e][tid] += red[e][tid + st];
        __syncthreads();
    }
    if (tid == 0) {
        float l[NEXP];
#pragma unroll
        for (int e = 0; e < NEXP; e++) l[e] = red[e][0];
        int i0 = 0;
#pragma unroll
        for (int e = 1; e < NEXP; e++) if (l[e] > l[i0]) i0 = e;
        int i1 = -1;
#pragma unroll
        for (int e = 0; e < NEXP; e++)
            if (e != i0 && (i1 < 0 || l[e] > l[i1])) i1 = e;
        float z = expf(l[i1] - l[i0]);
        float w0 = 1.0f / (1.0f + z);
        tope[tok * 2]     = i0;  wgt[tok * 2]     = w0;
        tope[tok * 2 + 1] = i1;  wgt[tok * 2 + 1] = 1.0f - w0;
    }
}

// ---------------- bucketize ----------------
__global__ void bucketize_k()
{
    __shared__ int sc[NEXP], cur[NEXP];
    int tid = threadIdx.x;
    if (tid < NEXP) sc[tid] = 0;
    __syncthreads();
    for (int a = tid; a < NASSIGN; a += 256) atomicAdd(&sc[g_tope[a]], 1);
    __syncthreads();
    if (tid == 0) {
        int o = 0;
        for (int e = 0; e < NEXP; e++) {
            g_cnt[e] = sc[e]; g_off[e] = o; cur[e] = o; o += sc[e];
        }
    }
    __syncthreads();
    for (int a = tid; a < NASSIGN; a += 256) {
        int e = g_tope[a];
        int p = atomicAdd(&cur[e], 1);
        g_perm[p] = a >> 1;
        g_slot[a] = p;
    }
}

// ---------------- combine (vectorized float4) ----------------
__global__ void combine_k(float* __restrict__ out, int total4)
{
    int idx = blockIdx.x * blockDim.x + threadIdx.x;
    if (idx >= total4) return;
    int e   = idx * 4;
    int tok = e >> 11;
    int d   = e & 2047;
    int s0 = g_slot[tok * 2],     s1 = g_slot[tok * 2 + 1];
    float w0 = g_wgt[tok * 2],    w1 = g_wgt[tok * 2 + 1];
    float4 a = *(const float4*)&g_inter[e];
    float4 b = *(const float4*)&g_eout[(size_t)s0 * DMODEL + d];
    float4 c = *(const float4*)&g_eout[(size_t)s1 * DMODEL + d];
    float4 r;
    r.x = a.x + w0 * b.x + w1 * c.x;
    r.y = a.y + w0 * b.y + w1 * c.y;
    r.z = a.z + w0 * b.z + w1 * c.z;
    r.w = a.w + w0 * b.w + w1 * c.w;
    *(float4*)&out[e] = r;
}

// =============================== launcher ===============================
extern "C" void kernel_launch(void* const* d_in, const int* in_sizes, int n_in,
                              void* d_out, int out_size)
{
    const float* inputs  = (const float*)d_in[0];
    const float* pre_s   = (const float*)d_in[1];
    const float* post_s  = (const float*)d_in[2];
    const float* wq      = (const float*)d_in[3];
    const float* wk      = (const float*)d_in[4];
    const float* wv      = (const float*)d_in[5];
    const float* wo_attn = (const float*)d_in[6];
    const float* gate_w  = (const float*)d_in[7];
    const float* wi0     = (const float*)d_in[8];
    const float* wi1     = (const float*)d_in[9];
    const float* wo_mlp  = (const float*)d_in[10];
    const int*   seg     = (const int*)d_in[11];
    const int*   pos     = (const int*)d_in[12];
    float* out = (float*)d_out;

    float *qkv, *inter, *h, *eout, *wgt;
    int *perm, *slot, *tope, *cnt, *off;
    fp16 *lnx,*ctx,*hh,*act,*qkvw,*wo,*w01,*wom,*qh,*kh,*vh;
    cudaGetSymbolAddress((void**)&qkv,  g_qkv);
    cudaGetSymbolAddress((void**)&inter,g_inter);
    cudaGetSymbolAddress((void**)&h,    g_hbuf);
    cudaGetSymbolAddress((void**)&eout, g_eout);
    cudaGetSymbolAddress((void**)&perm, g_perm);
    cudaGetSymbolAddress((void**)&slot, g_slot);
    cudaGetSymbolAddress((void**)&tope, g_tope);
    cudaGetSymbolAddress((void**)&wgt,  g_wgt);
    cudaGetSymbolAddress((void**)&cnt,  g_cnt);
    cudaGetSymbolAddress((void**)&off,  g_off);
    cudaGetSymbolAddress((void**)&lnx,  g_lnx);
    cudaGetSymbolAddress((void**)&ctx,  g_ctx);
    cudaGetSymbolAddress((void**)&hh,   g_hh);
    cudaGetSymbolAddress((void**)&act,  g_act);
    cudaGetSymbolAddress((void**)&qkvw, g_qkvw);
    cudaGetSymbolAddress((void**)&wo,   g_wo);
    cudaGetSymbolAddress((void**)&w01,  g_w01);
    cudaGetSymbolAddress((void**)&wom,  g_wom);
    cudaGetSymbolAddress((void**)&qh,   g_qh);
    cudaGetSymbolAddress((void**)&kh,   g_kh);
    cudaGetSymbolAddress((void**)&vh,   g_vh);

    cudaFuncSetAttribute(fp16_gemm_k, cudaFuncAttributeMaxDynamicSharedMemorySize,
                         SMEM_GEMM_BYTES);
    cudaFuncSetAttribute(flash2_k, cudaFuncAttributeMaxDynamicSharedMemorySize,
                         FLASH_SMEM_BYTES);

    // 0) weight converts (fp16, vectorized)
    {
        long long t4;
        t4 = (long long)DMODEL * DMODEL / 4;
        wcvt4_k<<<dim3((unsigned)((t4 + 255) / 256), 1), 256>>>(
            wq, qkvw, DMODEL, QKVN, 0, 0, 0, t4);
        t4 = (long long)DMODEL * (HKVN * HD) / 4;
        wcvt4_k<<<dim3((unsigned)((t4 + 255) / 256), 1), 256>>>(
            wk, qkvw, HKVN * HD, QKVN, 2048, 0, 0, t4);
        wcvt4_k<<<dim3((unsigned)((t4 + 255) / 256), 1), 256>>>(
            wv, qkvw, HKVN * HD, QKVN, 3072, 0, 0, t4);
        t4 = (long long)DMODEL * DMODEL / 4;
        wcvt4_k<<<dim3((unsigned)((t4 + 255) / 256), 1), 256>>>(
            wo_attn, wo, DMODEL, DMODEL, 0, 0, 0, t4);
        t4 = (long long)DMODEL * FDIM / 4;
        w01cvt_k<<<dim3((unsigned)((t4 + 255) / 256), NEXP), 256>>>(wi0, wi1, w01, t4);
        t4 = (long long)FDIM * DMODEL / 4;
        wcvt4_k<<<dim3((unsigned)((t4 + 255) / 256), NEXP), 256>>>(
            wo_mlp, wom, DMODEL, DMODEL, 0,
            (long long)FDIM * DMODEL, (long long)FDIM * DMODEL, t4);
    }

    // 1) pre-attention RMSNorm -> lnx fp16
    rmsnorm_split_k<<<NT, 256>>>(inputs, pre_s, nullptr, lnx);

    // 2) fused QKV projection -> qkv fp32
    fp16_gemm_k<<<dim3(QKVN/256, NT/128, 1), 256, SMEM_GEMM_BYTES>>>(
        lnx, qkvw, nullptr, qkv, nullptr,
        NT, QKVN, DMODEL, nullptr, nullptr, nullptr, 0, 0);

    // 3) RoPE + splits
    {
        int totq = NT * HQN * 64;
        rope1_k<<<(totq + 255) / 256, 256>>>(qkv, pos, 0, HQN,
            0.08838834764831845f, qh, totq);
        int totk = NT * HKVN * 64;
        rope1_k<<<(totk + 255) / 256, 256>>>(qkv, pos, 2048, HKVN, 1.0f, kh, totk);
        int totv4 = NT * HKVN * HD / 4;
        splitv1_k<<<(totv4 + 255) / 256, 256>>>(qkv, vh, totv4);
    }

    // 4) flash attention -> ctx fp16
    flash2_k<<<dim3(S_LEN/FQT, HQN, BATCH), 128, FLASH_SMEM_BYTES>>>(
        qh, kh, vh, seg, ctx);

    // 5) O projection + residual -> inter
    fp16_gemm_k<<<dim3(DMODEL/256, NT/128, 1), 256, SMEM_GEMM_BYTES>>>(
        ctx, wo, inputs, inter, nullptr,
        NT, DMODEL, DMODEL, nullptr, nullptr, nullptr, 0, 0);

    // 6) post-attention RMSNorm -> h fp32 + fp16
    rmsnorm_split_k<<<NT, 256>>>(inter, post_s, h, hh);

    // 7) gating
    gate_k<<<NT, 128>>>(h, gate_w, tope, wgt);

    // 8) bucketize
    bucketize_k<<<1, 256>>>();

    // 9) fused MoE up-projection + SiLU (interleaved wi0/wi1) -> act fp16
    fp16_gemm_k<<<dim3((2*FDIM)/256, NASSIGN/128, NEXP), 256, SMEM_GEMM_BYTES>>>(
        hh, w01, nullptr, nullptr, act,
        0, 2*FDIM, DMODEL, perm, cnt, off, (long long)DMODEL * 2 * FDIM, 1);

    // 10) MoE down-projection -> eout
    fp16_gemm_k<<<dim3(DMODEL/256, NASSIGN/128, NEXP), 256, SMEM_GEMM_BYTES>>>(
        act, wom, nullptr, eout, nullptr,
        0, DMODEL, FDIM, nullptr, cnt, off, (long long)FDIM * DMODEL, 0);

    // 11) combine
    combine_k<<<(NT * DMODEL / 4 + 255) / 256, 256>>>(out, NT * DMODEL / 4);
}

// round 9
// speedup vs baseline: 1.2267x; 1.2267x over previous
#include <cuda_runtime.h>
#include <cuda_fp16.h>
#include <cstdint>
#include <math.h>

#define NT      4096       // B*S tokens
#define DMODEL  2048
#define S_LEN   2048
#define BATCH   2
#define HQN     16
#define HKVN    8
#define HD      128
#define NEXP    8
#define FDIM    4096
#define NASSIGN (NT*2)
#define QKVN    4096       // 2048 q + 1024 k + 1024 v

typedef __half fp16;

// ---------------- scratch ----------------
__device__ float g_qkv [NT*QKVN];
__device__ float g_inter[NT*DMODEL];
__device__ float g_hbuf[NT*DMODEL];
__device__ float g_eout[NASSIGN*DMODEL];
__device__ int   g_perm[NASSIGN];
__device__ int   g_slot[NASSIGN];
__device__ int   g_tope[NASSIGN];
__device__ float g_wgt [NASSIGN];
__device__ int   g_cnt [NEXP];
__device__ int   g_off [NEXP];

// fp16 activation planes (single plane)
__device__ fp16 g_lnx [NT*DMODEL];
__device__ fp16 g_ctx [NT*DMODEL];
__device__ fp16 g_hh  [NT*DMODEL];
__device__ fp16 g_act [NASSIGN*FDIM];
// fp16 weights
__device__ fp16 g_qkvw[DMODEL*QKVN];
__device__ fp16 g_wo  [DMODEL*DMODEL];
__device__ fp16 g_w01 [(size_t)NEXP*DMODEL*2*FDIM];   // interleaved wi0/wi1
__device__ fp16 g_wom [(size_t)NEXP*FDIM*DMODEL];
// attention operands
__device__ fp16 g_qh[NT*HQN*HD];
__device__ fp16 g_kh[NT*HKVN*HD];
__device__ fp16 g_vh[NT*HKVN*HD];

__device__ __forceinline__ uint32_t packh2(fp16 a, fp16 b) {
    __half2 p; p.x = a; p.y = b;
    return *(uint32_t*)&p;
}
__device__ __forceinline__ void cp16(uint32_t dst, const void* src) {
    asm volatile("cp.async.cg.shared.global [%0], [%1], 16;" :: "r"(dst), "l"(src));
}
__device__ __forceinline__ void cp16_zero(uint32_t dst, const void* src) {
    asm volatile("cp.async.cg.shared.global [%0], [%1], 16, 0;" :: "r"(dst), "l"(src));
}
#define CP_COMMIT() asm volatile("cp.async.commit_group;" ::: "memory")

__device__ __forceinline__ void ldm_x4(uint32_t* r, uint32_t addr) {
    asm volatile("ldmatrix.sync.aligned.m8n8.x4.shared.b16 {%0,%1,%2,%3}, [%4];"
        : "=r"(r[0]), "=r"(r[1]), "=r"(r[2]), "=r"(r[3]) : "r"(addr));
}
__device__ __forceinline__ void ldm_x2t(uint32_t* r, uint32_t addr) {
    asm volatile("ldmatrix.sync.aligned.m8n8.x2.trans.shared.b16 {%0,%1}, [%2];"
        : "=r"(r[0]), "=r"(r[1]) : "r"(addr));
}
__device__ __forceinline__ void mma_f16(float* c, const uint32_t* a, const uint32_t* b) {
    asm volatile(
        "mma.sync.aligned.m16n8k16.row.col.f32.f16.f16.f32 "
        "{%0,%1,%2,%3}, {%4,%5,%6,%7}, {%8,%9}, {%0,%1,%2,%3};"
        : "+f"(c[0]), "+f"(c[1]), "+f"(c[2]), "+f"(c[3])
        : "r"(a[0]), "r"(a[1]), "r"(a[2]), "r"(a[3]), "r"(b[0]), "r"(b[1]));
}

// ---------------- vectorized weight convert (float4 -> 4 fp16) ----------------
__global__ void wcvt4_k(const float* __restrict__ src, fp16* __restrict__ dst,
                        int ncol, int dstStride, int colOff,
                        long long srcZ, long long dstZ, long long total4)
{
    long long i = (long long)blockIdx.x * blockDim.x + threadIdx.x;
    if (i >= total4) return;
    int z = blockIdx.y;
    const float4* s = (const float4*)(src + (long long)z * srcZ);
    fp16* d = dst + (long long)z * dstZ;
    float4 v = s[i];
    long long e = i * 4;
    int kr = (int)(e / ncol);
    int n  = (int)(e % ncol);
    uint32_t* w = (uint32_t*)(d + (long long)kr * dstStride + colOff + n);
    w[0] = packh2(__float2half(v.x), __float2half(v.y));
    w[1] = packh2(__float2half(v.z), __float2half(v.w));
}

// ---------------- fused wi0/wi1 interleave convert ----------------
__global__ void w01cvt_k(const float* __restrict__ wi0, const float* __restrict__ wi1,
                         fp16* __restrict__ dst, long long total4)
{
    long long i = (long long)blockIdx.x * blockDim.x + threadIdx.x;
    if (i >= total4) return;
    int z = blockIdx.y;
    const float4* s0 = (const float4*)(wi0 + (long long)z * DMODEL * FDIM);
    const float4* s1 = (const float4*)(wi1 + (long long)z * DMODEL * FDIM);
    float4 a = s0[i], b = s1[i];
    uint32_t* w = (uint32_t*)(dst + (long long)z * DMODEL * 2 * FDIM + i * 8);
    w[0] = packh2(__float2half(a.x), __float2half(b.x));
    w[1] = packh2(__float2half(a.y), __float2half(b.y));
    w[2] = packh2(__float2half(a.z), __float2half(b.z));
    w[3] = packh2(__float2half(a.w), __float2half(b.w));
}

// ---------------- RMSNorm (+optional fp32 out, fp16 out) ----------------
__global__ void rmsnorm_split_k(const float* __restrict__ x, const float* __restrict__ sc,
                                float* __restrict__ yf, fp16* __restrict__ yh)
{
    int row = blockIdx.x;
    int tid = threadIdx.x;
    const float* xr = x + (size_t)row * DMODEL;
    float ss = 0.f;
    for (int d = tid; d < DMODEL; d += 256) { float v = xr[d]; ss += v * v; }
    __shared__ float red[256];
    red[tid] = ss; __syncthreads();
    for (int st = 128; st > 0; st >>= 1) {
        if (tid < st) red[tid] += red[tid + st];
        __syncthreads();
    }
    float inv = rsqrtf(red[0] / (float)DMODEL + 1e-6f);
    size_t base = (size_t)row * DMODEL;
    for (int d = tid; d < DMODEL; d += 256) {
        float v = xr[d] * inv * sc[d];
        if (yf) yf[base + d] = v;
        yh[base + d] = __float2half(v);
    }
}

// ================= fp16 tensor-core GEMM (R6 config: 128x128, occ 2) ==========
#define ASTR 40
#define BSTR 136
#define OFF_A(s) ((s)*5120)
#define OFF_B(s) (10240 + (s)*4352)
#define SMEM_GEMM_BYTES (18944*2)

__global__ __launch_bounds__(256, 2)
void fp16_gemm_k(const fp16* __restrict__ Ag, const fp16* __restrict__ Bg,
                 const float* __restrict__ res, float* __restrict__ Cf,
                 fp16* __restrict__ SH,
                 int M, int N, int K,
                 const int* __restrict__ perm,
                 const int* __restrict__ cnts, const int* __restrict__ offs,
                 long long strideB, int mode)
{
    extern __shared__ fp16 sm[];
    int rowBase = 0;
    const fp16* B = Bg;
    if (cnts) {
        int e = blockIdx.z;
        M = cnts[e];
        rowBase = offs[e];
        B = Bg + (long long)e * strideB;
    }
    int bm = blockIdx.y * 128;
    if (bm >= M) return;
    int bn = blockIdx.x * 128;

    int tid  = threadIdx.x;
    int lane = tid & 31;
    int w    = tid >> 5;
    int wm   = w & 1;
    int wn   = w >> 1;

    uint32_t smBase = (uint32_t)__cvta_generic_to_shared(sm);
    uint32_t aLane  = ((lane & 15) * ASTR + (lane >> 4) * 8) * 2;
    uint32_t bLane  = ((lane & 15) * BSTR) * 2;

    int rA  = tid >> 1;
    int ac0 = (tid & 1) * 16;
    int aIdx = -1;
    if (bm + rA < M) { int r = rowBase + bm + rA; aIdx = perm ? perm[r] : r; }

    int rB  = tid >> 3;
    int bc0 = (tid & 7) * 8;

    float acc[4][4][4];
#pragma unroll
    for (int i = 0; i < 4; i++)
#pragma unroll
        for (int j = 0; j < 4; j++)
#pragma unroll
            for (int c = 0; c < 4; c++) acc[i][j][c] = 0.f;

    const int NKT = K >> 5;

    auto prefetch = [&](int kt, int st) {
        int k0 = kt << 5;
        uint32_t dA = smBase + (OFF_A(st) + rA * ASTR + ac0) * 2;
        if (aIdx >= 0) {
            const fp16* sa = Ag + (size_t)aIdx * K + k0 + ac0;
            cp16(dA, sa);      cp16(dA + 16, sa + 8);
        } else {
            cp16_zero(dA, Ag); cp16_zero(dA + 16, Ag);
        }
        uint32_t dB = smBase + (OFF_B(st) + rB * BSTR + bc0) * 2;
        const fp16* sb = B + (size_t)(k0 + rB) * N + bn + bc0;
        cp16(dB, sb);       cp16(dB + 128, sb + 64);
    };

    prefetch(0, 0);
    CP_COMMIT();

    for (int kt = 0; kt < NKT; kt++) {
        int st = kt & 1;
        if (kt + 1 < NKT) {
            prefetch(kt + 1, st ^ 1);
            CP_COMMIT();
            asm volatile("cp.async.wait_group 1;" ::: "memory");
        } else {
            asm volatile("cp.async.wait_group 0;" ::: "memory");
        }
        __syncthreads();

        uint32_t aBase = smBase + (OFF_A(st) + wm * 64 * ASTR) * 2 + aLane;
        uint32_t bBase = smBase + (OFF_B(st)) * 2 + wn * 32 * 2 + bLane;

#pragma unroll
        for (int ks = 0; ks < 2; ks++) {
            uint32_t ah[4][4];
#pragma unroll
            for (int mf = 0; mf < 4; mf++) {
                uint32_t off = mf * (16 * ASTR * 2) + ks * 32;
                ldm_x4(ah[mf], aBase + off);
            }
            uint32_t bh[4][2];
#pragma unroll
            for (int nf = 0; nf < 4; nf++) {
                uint32_t off = nf * 16 + ks * (16 * BSTR * 2);
                ldm_x2t(bh[nf], bBase + off);
            }
#pragma unroll
            for (int mf = 0; mf < 4; mf++)
#pragma unroll
                for (int nf = 0; nf < 4; nf++)
                    mma_f16(acc[mf][nf], ah[mf], bh[nf]);
        }
        __syncthreads();
    }

    int g   = lane >> 2;
    int tig = lane & 3;
#pragma unroll
    for (int mf = 0; mf < 4; mf++) {
        int row0 = bm + wm * 64 + mf * 16 + g;
        int row1 = row0 + 8;
#pragma unroll
        for (int nf = 0; nf < 4; nf++) {
            int col = bn + wn * 32 + nf * 8 + tig * 2;
            if (mode == 0) {
                if (row0 < M) {
                    size_t o = (size_t)(rowBase + row0) * N + col;
                    float2 v = make_float2(acc[mf][nf][0], acc[mf][nf][1]);
                    if (res) { float2 r = *(const float2*)&res[o]; v.x += r.x; v.y += r.y; }
                    *(float2*)&Cf[o] = v;
                }
                if (row1 < M) {
                    size_t o = (size_t)(rowBase + row1) * N + col;
                    float2 v = make_float2(acc[mf][nf][2], acc[mf][nf][3]);
                    if (res) { float2 r = *(const float2*)&res[o]; v.x += r.x; v.y += r.y; }
                    *(float2*)&Cf[o] = v;
                }
            } else {
                // interleaved silu: even col = gate (wi0), odd col = value (wi1)
                int f = col >> 1;
                if (row0 < M) {
                    size_t o = (size_t)(rowBase + row0) * (size_t)(N >> 1) + f;
                    float a = acc[mf][nf][0], b = acc[mf][nf][1];
                    SH[o] = __float2half((a / (1.0f + __expf(-a))) * b);
                }
                if (row1 < M) {
                    size_t o = (size_t)(rowBase + row1) * (size_t)(N >> 1) + f;
                    float a = acc[mf][nf][2], b = acc[mf][nf][3];
                    SH[o] = __float2half((a / (1.0f + __expf(-a))) * b);
                }
            }
        }
    }
}

// ---------------- RoPE -> single fp16 plane ----------------
__global__ void rope1_k(const float* __restrict__ qkv, const int* __restrict__ pos,
                        int srcOff, int nheads, float scale,
                        fp16* __restrict__ outH, int total)
{
    int idx = blockIdx.x * blockDim.x + threadIdx.x;
    if (idx >= total) return;
    int i   = idx & 63;
    int th  = idx >> 6;
    int h   = th % nheads;
    int tok = th / nheads;
    float freq = powf(10000.0f, -(float)i / 64.0f);
    float ang = (float)pos[tok] * freq;
    float c = cosf(ang), s = sinf(ang);
    const float* row = qkv + (size_t)tok * QKVN + srcOff + h * HD;
    float x1 = row[i], x2 = row[i + 64];
    size_t o = (size_t)tok * (nheads * HD) + h * HD;
    outH[o + i]      = __float2half((x1 * c - x2 * s) * scale);
    outH[o + i + 64] = __float2half((x2 * c + x1 * s) * scale);
}

__global__ void splitv1_k(const float* __restrict__ qkv, fp16* __restrict__ vh, int total4)
{
    int idx = blockIdx.x * blockDim.x + threadIdx.x;
    if (idx >= total4) return;
    int e   = idx * 4;
    int tok = e >> 10;
    int d   = e & 1023;
    float4 v = *(const float4*)&qkv[(size_t)tok * QKVN + 3072 + d];
    uint32_t* w = (uint32_t*)&vh[e];
    w[0] = packh2(__float2half(v.x), __float2half(v.y));
    w[1] = packh2(__float2half(v.z), __float2half(v.w));
}

// ================= fp16 flash attention =================
#define FQT 64
#define FKT 32
#define FSTR 136
#define F_Q 0
#define F_K(s) (8704 + (s)*4352)
#define F_V(s) (17408 + (s)*4352)
#define FLASH_SMEM_BYTES (26112*2)

__global__ __launch_bounds__(128)
void flash2_k(const fp16* __restrict__ Qh,
              const fp16* __restrict__ Kh, const fp16* __restrict__ Vh,
              const int* __restrict__ seg, fp16* __restrict__ Oh)
{
    extern __shared__ fp16 fsm[];
    __shared__ int Sq[FQT];
    __shared__ int Sk[2][FKT];

    int tid  = threadIdx.x;
    int lane = tid & 31;
    int w    = tid >> 5;
    int g    = lane >> 2;
    int tig  = lane & 3;

    int q0  = blockIdx.x * FQT;
    int h   = blockIdx.y;
    int b   = blockIdx.z;
    int tok0 = b * S_LEN;
    int hk  = h >> 1;

    uint32_t smBase = (uint32_t)__cvta_generic_to_shared(fsm);

    {
        int r  = tid >> 1;
        int c0 = (tid & 1) * 64;
        const fp16* sq = Qh + (size_t)(tok0 + q0 + r) * (HQN * HD) + h * HD + c0;
        uint32_t dq = smBase + (F_Q + r * FSTR + c0) * 2;
#pragma unroll
        for (int j = 0; j < 8; j++) cp16(dq + j * 16, sq + j * 8);
    }
    if (tid < FQT) Sq[tid] = seg[tok0 + q0 + tid];

    auto prefetch = [&](int kt, int st) {
        int k0 = kt * FKT;
        int r  = tid >> 2;
        int c0 = (tid & 3) * 32;
        size_t gbase = (size_t)(tok0 + k0 + r) * (HKVN * HD) + hk * HD + c0;
        uint32_t dk = smBase + (F_K(st) + r * FSTR + c0) * 2;
        uint32_t dv = smBase + (F_V(st) + r * FSTR + c0) * 2;
#pragma unroll
        for (int j = 0; j < 4; j++) {
            cp16(dk + j * 16, Kh + gbase + j * 8);
            cp16(dv + j * 16, Vh + gbase + j * 8);
        }
        if (tid < FKT) Sk[st][tid] = seg[tok0 + k0 + tid];
    };

    prefetch(0, 0);
    CP_COMMIT();

    float of[16][4];
#pragma unroll
    for (int nf = 0; nf < 16; nf++)
#pragma unroll
        for (int c = 0; c < 4; c++) of[nf][c] = 0.f;
    float m0 = -1e9f, m1 = -1e9f, l0 = 0.f, l1 = 0.f;

    uint32_t qAddr = smBase + (F_Q + (w * 16 + (lane & 15)) * FSTR + (lane >> 4) * 8) * 2;
    int ktokoff = (lane & 7) + ((lane >> 4) << 3);
    int kdhalf  = ((lane >> 3) & 1) * 8;
    int vrow    = lane & 15;

    int ktend = (q0 + FQT - 1) / FKT;
    int myrow0 = q0 + w * 16 + g;
    int myrow1 = myrow0 + 8;
    int sq0 = 0, sq1 = 0;

    for (int kt = 0; kt <= ktend; kt++) {
        int st = kt & 1;
        if (kt + 1 <= ktend) {
            prefetch(kt + 1, st ^ 1);
            CP_COMMIT();
            asm volatile("cp.async.wait_group 1;" ::: "memory");
        } else {
            asm volatile("cp.async.wait_group 0;" ::: "memory");
        }
        __syncthreads();
        if (kt == 0) { sq0 = Sq[w * 16 + g]; sq1 = Sq[w * 16 + g + 8]; }
        int k0 = kt * FKT;

        float sf[4][4];
#pragma unroll
        for (int nf = 0; nf < 4; nf++)
#pragma unroll
            for (int c = 0; c < 4; c++) sf[nf][c] = 0.f;

        uint32_t kBase = smBase + (F_K(st) + ktokoff * FSTR + kdhalf) * 2;

#pragma unroll
        for (int kk = 0; kk < 8; kk++) {
            uint32_t qh4[4];
            ldm_x4(qh4, qAddr + kk * 32);
#pragma unroll
            for (int p = 0; p < 2; p++) {
                uint32_t kh4[4];
                uint32_t off = (p * 16 * FSTR + kk * 16) * 2;
                ldm_x4(kh4, kBase + off);
                mma_f16(sf[2 * p],     qh4, kh4);
                mma_f16(sf[2 * p + 1], qh4, kh4 + 2);
            }
        }

#pragma unroll
        for (int nf = 0; nf < 4; nf++) {
            int c0g = k0 + nf * 8 + 2 * tig;
            int sk0 = Sk[st][nf * 8 + 2 * tig];
            int sk1 = Sk[st][nf * 8 + 2 * tig + 1];
            if (c0g > myrow0     || sk0 != sq0) sf[nf][0] = -1e9f;
            if (c0g + 1 > myrow0 || sk1 != sq0) sf[nf][1] = -1e9f;
            if (c0g > myrow1     || sk0 != sq1) sf[nf][2] = -1e9f;
            if (c0g + 1 > myrow1 || sk1 != sq1) sf[nf][3] = -1e9f;
        }
        float mx0 = -1e9f, mx1 = -1e9f;
#pragma unroll
        for (int nf = 0; nf < 4; nf++) {
            mx0 = fmaxf(mx0, fmaxf(sf[nf][0], sf[nf][1]));
            mx1 = fmaxf(mx1, fmaxf(sf[nf][2], sf[nf][3]));
        }
        mx0 = fmaxf(mx0, __shfl_xor_sync(0xffffffff, mx0, 1));
        mx0 = fmaxf(mx0, __shfl_xor_sync(0xffffffff, mx0, 2));
        mx1 = fmaxf(mx1, __shfl_xor_sync(0xffffffff, mx1, 1));
        mx1 = fmaxf(mx1, __shfl_xor_sync(0xffffffff, mx1, 2));
        float mn0 = fmaxf(m0, mx0), mn1 = fmaxf(m1, mx1);
        float al0 = __expf(m0 - mn0), al1 = __expf(m1 - mn1);
        m0 = mn0; m1 = mn1;
        float ls0 = 0.f, ls1 = 0.f;
#pragma unroll
        for (int nf = 0; nf < 4; nf++) {
            sf[nf][0] = __expf(sf[nf][0] - mn0);
            sf[nf][1] = __expf(sf[nf][1] - mn0);
            sf[nf][2] = __expf(sf[nf][2] - mn1);
            sf[nf][3] = __expf(sf[nf][3] - mn1);
            ls0 += sf[nf][0] + sf[nf][1];
            ls1 += sf[nf][2] + sf[nf][3];
        }
        l0 = l0 * al0 + ls0;
        l1 = l1 * al1 + ls1;
#pragma unroll
        for (int nf = 0; nf < 16; nf++) {
            of[nf][0] *= al0; of[nf][1] *= al0;
            of[nf][2] *= al1; of[nf][3] *= al1;
        }

        uint32_t vBase = smBase + (F_V(st) + vrow * FSTR) * 2;
#pragma unroll
        for (int t = 0; t < 2; t++) {
            uint32_t pah[4];
#pragma unroll
            for (int q = 0; q < 2; q++) {
                pah[2 * q]     = packh2(__float2half(sf[2 * t + q][0]),
                                        __float2half(sf[2 * t + q][1]));
                pah[2 * q + 1] = packh2(__float2half(sf[2 * t + q][2]),
                                        __float2half(sf[2 * t + q][3]));
            }
#pragma unroll
            for (int nf = 0; nf < 16; nf++) {
                uint32_t vh2[2];
                uint32_t off = (t * 16 * FSTR + nf * 8) * 2;
                ldm_x2t(vh2, vBase + off);
                mma_f16(of[nf], pah, vh2);
            }
        }
        __syncthreads();
    }

    l0 += __shfl_xor_sync(0xffffffff, l0, 1);
    l0 += __shfl_xor_sync(0xffffffff, l0, 2);
    l1 += __shfl_xor_sync(0xffffffff, l1, 1);
    l1 += __shfl_xor_sync(0xffffffff, l1, 2);
    float i0 = 1.0f / l0, i1 = 1.0f / l1;
    size_t r0 = (size_t)(tok0 + myrow0) * DMODEL + h * HD;
    size_t r1 = (size_t)(tok0 + myrow1) * DMODEL + h * HD;
#pragma unroll
    for (int nf = 0; nf < 16; nf++) {
        int col = nf * 8 + 2 * tig;
        *(uint32_t*)&Oh[r0 + col] = packh2(__float2half(of[nf][0] * i0),
                                           __float2half(of[nf][1] * i0));
        *(uint32_t*)&Oh[r1 + col] = packh2(__float2half(of[nf][2] * i1),
                                           __float2half(of[nf][3] * i1));
    }
}

// ---------------- gating ----------------
__global__ void gate_k(const float* __restrict__ h, const float* __restrict__ gw,
                       int* __restrict__ tope, float* __restrict__ wgt)
{
    int tok = blockIdx.x;
    int tid = threadIdx.x;
    float s[NEXP];
#pragma unroll
    for (int e = 0; e < NEXP; e++) s[e] = 0.f;
    const float* hr = h + (size_t)tok * DMODEL;
    for (int d = tid; d < DMODEL; d += 128) {
        float hv = hr[d];
#pragma unroll
        for (int e = 0; e < NEXP; e++) s[e] += hv * gw[d * NEXP + e];
    }
    __shared__ float red[NEXP][128];
#pragma unroll
    for (int e = 0; e < NEXP; e++) red[e][tid] = s[e];
    __syncthreads();
    for (int st = 64; st > 0; st >>= 1) {
        if (tid < st)
#pragma unroll
            for (int e = 0; e < NEXP; e++) red[e][tid] += red[e][tid + st];
        __syncthreads();
    }
    if (tid == 0) {
        float l[NEXP];
#pragma unroll
        for (int e = 0; e < NEXP; e++) l[e] = red[e][0];
        int i0 = 0;
#pragma unroll
        for (int e = 1; e < NEXP; e++) if (l[e] > l[i0]) i0 = e;
        int i1 = -1;
#pragma unroll
        for (int e = 0; e < NEXP; e++)
            if (e != i0 && (i1 < 0 || l[e] > l[i1])) i1 = e;
        float z = expf(l[i1] - l[i0]);
        float w0 = 1.0f / (1.0f + z);
        tope[tok * 2]     = i0;  wgt[tok * 2]     = w0;
        tope[tok * 2 + 1] = i1;  wgt[tok * 2 + 1] = 1.0f - w0;
    }
}

// ---------------- bucketize ----------------
__global__ void bucketize_k()
{
    __shared__ int sc[NEXP], cur[NEXP];
    int tid = threadIdx.x;
    if (tid < NEXP) sc[tid] = 0;
    __syncthreads();
    for (int a = tid; a < NASSIGN; a += 256) atomicAdd(&sc[g_tope[a]], 1);
    __syncthreads();
    if (tid == 0) {
        int o = 0;
        for (int e = 0; e < NEXP; e++) {
            g_cnt[e] = sc[e]; g_off[e] = o; cur[e] = o; o += sc[e];
        }
    }
    __syncthreads();
    for (int a = tid; a < NASSIGN; a += 256) {
        int e = g_tope[a];
        int p = atomicAdd(&cur[e], 1);
        g_perm[p] = a >> 1;
        g_slot[a] = p;
    }
}

// ---------------- combine (vectorized float4) ----------------
__global__ void combine_k(float* __restrict__ out, int total4)
{
    int idx = blockIdx.x * blockDim.x + threadIdx.x;
    if (idx >= total4) return;
    int e   = idx * 4;
    int tok = e >> 11;
    int d   = e & 2047;
    int s0 = g_slot[tok * 2],     s1 = g_slot[tok * 2 + 1];
    float w0 = g_wgt[tok * 2],    w1 = g_wgt[tok * 2 + 1];
    float4 a = *(const float4*)&g_inter[e];
    float4 b = *(const float4*)&g_eout[(size_t)s0 * DMODEL + d];
    float4 c = *(const float4*)&g_eout[(size_t)s1 * DMODEL + d];
    float4 r;
    r.x = a.x + w0 * b.x + w1 * c.x;
    r.y = a.y + w0 * b.y + w1 * c.y;
    r.z = a.z + w0 * b.z + w1 * c.z;
    r.w = a.w + w0 * b.w + w1 * c.w;
    *(float4*)&out[e] = r;
}

// =============================== launcher ===============================
extern "C" void kernel_launch(void* const* d_in, const int* in_sizes, int n_in,
                              void* d_out, int out_size)
{
    const float* inputs  = (const float*)d_in[0];
    const float* pre_s   = (const float*)d_in[1];
    const float* post_s  = (const float*)d_in[2];
    const float* wq      = (const float*)d_in[3];
    const float* wk      = (const float*)d_in[4];
    const float* wv      = (const float*)d_in[5];
    const float* wo_attn = (const float*)d_in[6];
    const float* gate_w  = (const float*)d_in[7];
    const float* wi0     = (const float*)d_in[8];
    const float* wi1     = (const float*)d_in[9];
    const float* wo_mlp  = (const float*)d_in[10];
    const int*   seg     = (const int*)d_in[11];
    const int*   pos     = (const int*)d_in[12];
    float* out = (float*)d_out;

    float *qkv, *inter, *h, *eout, *wgt;
    int *perm, *slot, *tope, *cnt, *off;
    fp16 *lnx,*ctx,*hh,*act,*qkvw,*wo,*w01,*wom,*qh,*kh,*vh;
    cudaGetSymbolAddress((void**)&qkv,  g_qkv);
    cudaGetSymbolAddress((void**)&inter,g_inter);
    cudaGetSymbolAddress((void**)&h,    g_hbuf);
    cudaGetSymbolAddress((void**)&eout, g_eout);
    cudaGetSymbolAddress((void**)&perm, g_perm);
    cudaGetSymbolAddress((void**)&slot, g_slot);
    cudaGetSymbolAddress((void**)&tope, g_tope);
    cudaGetSymbolAddress((void**)&wgt,  g_wgt);
    cudaGetSymbolAddress((void**)&cnt,  g_cnt);
    cudaGetSymbolAddress((void**)&off,  g_off);
    cudaGetSymbolAddress((void**)&lnx,  g_lnx);
    cudaGetSymbolAddress((void**)&ctx,  g_ctx);
    cudaGetSymbolAddress((void**)&hh,   g_hh);
    cudaGetSymbolAddress((void**)&act,  g_act);
    cudaGetSymbolAddress((void**)&qkvw, g_qkvw);
    cudaGetSymbolAddress((void**)&wo,   g_wo);
    cudaGetSymbolAddress((void**)&w01,  g_w01);
    cudaGetSymbolAddress((void**)&wom,  g_wom);
    cudaGetSymbolAddress((void**)&qh,   g_qh);
    cudaGetSymbolAddress((void**)&kh,   g_kh);
    cudaGetSymbolAddress((void**)&vh,   g_vh);

    cudaFuncSetAttribute(fp16_gemm_k, cudaFuncAttributeMaxDynamicSharedMemorySize,
                         SMEM_GEMM_BYTES);
    cudaFuncSetAttribute(flash2_k, cudaFuncAttributeMaxDynamicSharedMemorySize,
                         FLASH_SMEM_BYTES);

    // 0) weight converts (fp16, vectorized)
    {
        long long t4;
        t4 = (long long)DMODEL * DMODEL / 4;
        wcvt4_k<<<dim3((unsigned)((t4 + 255) / 256), 1), 256>>>(
            wq, qkvw, DMODEL, QKVN, 0, 0, 0, t4);
        t4 = (long long)DMODEL * (HKVN * HD) / 4;
        wcvt4_k<<<dim3((unsigned)((t4 + 255) / 256), 1), 256>>>(
            wk, qkvw, HKVN * HD, QKVN, 2048, 0, 0, t4);
        wcvt4_k<<<dim3((unsigned)((t4 + 255) / 256), 1), 256>>>(
            wv, qkvw, HKVN * HD, QKVN, 3072, 0, 0, t4);
        t4 = (long long)DMODEL * DMODEL / 4;
        wcvt4_k<<<dim3((unsigned)((t4 + 255) / 256), 1), 256>>>(
            wo_attn, wo, DMODEL, DMODEL, 0, 0, 0, t4);
        t4 = (long long)DMODEL * FDIM / 4;
        w01cvt_k<<<dim3((unsigned)((t4 + 255) / 256), NEXP), 256>>>(wi0, wi1, w01, t4);
        t4 = (long long)FDIM * DMODEL / 4;
        wcvt4_k<<<dim3((unsigned)((t4 + 255) / 256), NEXP), 256>>>(
            wo_mlp, wom, DMODEL, DMODEL, 0,
            (long long)FDIM * DMODEL, (long long)FDIM * DMODEL, t4);
    }

    // 1) pre-attention RMSNorm -> lnx fp16
    rmsnorm_split_k<<<NT, 256>>>(inputs, pre_s, nullptr, lnx);

    // 2) fused QKV projection -> qkv fp32
    fp16_gemm_k<<<dim3(QKVN/128, NT/128, 1), 256, SMEM_GEMM_BYTES>>>(
        lnx, qkvw, nullptr, qkv, nullptr,
        NT, QKVN, DMODEL, nullptr, nullptr, nullptr, 0, 0);

    // 3) RoPE + splits
    {
        int totq = NT * HQN * 64;
        rope1_k<<<(totq + 255) / 256, 256>>>(qkv, pos, 0, HQN,
            0.08838834764831845f, qh, totq);
        int totk = NT * HKVN * 64;
        rope1_k<<<(totk + 255) / 256, 256>>>(qkv, pos, 2048, HKVN, 1.0f, kh, totk);
        int totv4 = NT * HKVN * HD / 4;
        splitv1_k<<<(totv4 + 255) / 256, 256>>>(qkv, vh, totv4);
    }

    // 4) flash attention -> ctx fp16
    flash2_k<<<dim3(S_LEN/FQT, HQN, BATCH), 128, FLASH_SMEM_BYTES>>>(
        qh, kh, vh, seg, ctx);

    // 5) O projection + residual -> inter
    fp16_gemm_k<<<dim3(DMODEL/128, NT/128, 1), 256, SMEM_GEMM_BYTES>>>(
        ctx, wo, inputs, inter, nullptr,
        NT, DMODEL, DMODEL, nullptr, nullptr, nullptr, 0, 0);

    // 6) post-attention RMSNorm -> h fp32 + fp16
    rmsnorm_split_k<<<NT, 256>>>(inter, post_s, h, hh);

    // 7) gating
    gate_k<<<NT, 128>>>(h, gate_w, tope, wgt);

    // 8) bucketize
    bucketize_k<<<1, 256>>>();

    // 9) fused MoE up-projection + SiLU (interleaved wi0/wi1) -> act fp16
    fp16_gemm_k<<<dim3((2*FDIM)/128, NASSIGN/128, NEXP), 256, SMEM_GEMM_BYTES>>>(
        hh, w01, nullptr, nullptr, act,
        0, 2*FDIM, DMODEL, perm, cnt, off, (long long)DMODEL * 2 * FDIM, 1);

    // 10) MoE down-projection -> eout
    fp16_gemm_k<<<dim3(DMODEL/128, NASSIGN/128, NEXP), 256, SMEM_GEMM_BYTES>>>(
        act, wom, nullptr, eout, nullptr,
        0, DMODEL, FDIM, nullptr, cnt, off, (long long)FDIM * DMODEL, 0);

    // 11) combine
    combine_k<<<(NT * DMODEL / 4 + 255) / 256, 256>>>(out, NT * DMODEL / 4);
}

// round 10
// speedup vs baseline: 1.3762x; 1.1219x over previous
#include <cuda_runtime.h>
#include <cuda_fp16.h>
#include <cstdint>
#include <math.h>

#define NT      4096       // B*S tokens
#define DMODEL  2048
#define S_LEN   2048
#define BATCH   2
#define HQN     16
#define HKVN    8
#define HD      128
#define NEXP    8
#define FDIM    4096
#define NASSIGN (NT*2)
#define QKVN    4096       // 2048 q + 1024 k + 1024 v

typedef __half fp16;

// ---------------- scratch ----------------
__device__ float g_inter[NT*DMODEL];
__device__ float g_hbuf[NT*DMODEL];
__device__ float g_eout[NASSIGN*DMODEL];
__device__ int   g_perm[NASSIGN];
__device__ int   g_slot[NASSIGN];
__device__ int   g_tope[NASSIGN];
__device__ float g_wgt [NASSIGN];
__device__ int   g_cnt [NEXP];
__device__ int   g_off [NEXP];

// fp16 activation planes
__device__ fp16 g_qkv16[NT*QKVN];       // q|k|v concat, roped in place
__device__ fp16 g_lnx [NT*DMODEL];
__device__ fp16 g_ctx [NT*DMODEL];
__device__ fp16 g_hh  [NT*DMODEL];
__device__ fp16 g_act [NASSIGN*FDIM];
// fp16 weights
__device__ fp16 g_qkvw[DMODEL*QKVN];
__device__ fp16 g_wo  [DMODEL*DMODEL];
__device__ fp16 g_w01 [(size_t)NEXP*DMODEL*2*FDIM];   // interleaved wi0/wi1
__device__ fp16 g_wom [(size_t)NEXP*FDIM*DMODEL];

__device__ __forceinline__ uint32_t packh2(fp16 a, fp16 b) {
    __half2 p; p.x = a; p.y = b;
    return *(uint32_t*)&p;
}
__device__ __forceinline__ void cp16(uint32_t dst, const void* src) {
    asm volatile("cp.async.cg.shared.global [%0], [%1], 16;" :: "r"(dst), "l"(src));
}
__device__ __forceinline__ void cp16_zero(uint32_t dst, const void* src) {
    asm volatile("cp.async.cg.shared.global [%0], [%1], 16, 0;" :: "r"(dst), "l"(src));
}
#define CP_COMMIT() asm volatile("cp.async.commit_group;" ::: "memory")

__device__ __forceinline__ void ldm_x4(uint32_t* r, uint32_t addr) {
    asm volatile("ldmatrix.sync.aligned.m8n8.x4.shared.b16 {%0,%1,%2,%3}, [%4];"
        : "=r"(r[0]), "=r"(r[1]), "=r"(r[2]), "=r"(r[3]) : "r"(addr));
}
__device__ __forceinline__ void ldm_x2t(uint32_t* r, uint32_t addr) {
    asm volatile("ldmatrix.sync.aligned.m8n8.x2.trans.shared.b16 {%0,%1}, [%2];"
        : "=r"(r[0]), "=r"(r[1]) : "r"(addr));
}
__device__ __forceinline__ void mma_f16(float* c, const uint32_t* a, const uint32_t* b) {
    asm volatile(
        "mma.sync.aligned.m16n8k16.row.col.f32.f16.f16.f32 "
        "{%0,%1,%2,%3}, {%4,%5,%6,%7}, {%8,%9}, {%0,%1,%2,%3};"
        : "+f"(c[0]), "+f"(c[1]), "+f"(c[2]), "+f"(c[3])
        : "r"(a[0]), "r"(a[1]), "r"(a[2]), "r"(a[3]), "r"(b[0]), "r"(b[1]));
}

// ---------------- vectorized weight convert (float4 -> 4 fp16) ----------------
__global__ void wcvt4_k(const float* __restrict__ src, fp16* __restrict__ dst,
                        int ncol, int dstStride, int colOff,
                        long long srcZ, long long dstZ, long long total4)
{
    long long i = (long long)blockIdx.x * blockDim.x + threadIdx.x;
    if (i >= total4) return;
    int z = blockIdx.y;
    const float4* s = (const float4*)(src + (long long)z * srcZ);
    fp16* d = dst + (long long)z * dstZ;
    float4 v = s[i];
    long long e = i * 4;
    int kr = (int)(e / ncol);
    int n  = (int)(e % ncol);
    uint32_t* w = (uint32_t*)(d + (long long)kr * dstStride + colOff + n);
    w[0] = packh2(__float2half(v.x), __float2half(v.y));
    w[1] = packh2(__float2half(v.z), __float2half(v.w));
}

// ---------------- fused wi0/wi1 interleave convert ----------------
__global__ void w01cvt_k(const float* __restrict__ wi0, const float* __restrict__ wi1,
                         fp16* __restrict__ dst, long long total4)
{
    long long i = (long long)blockIdx.x * blockDim.x + threadIdx.x;
    if (i >= total4) return;
    int z = blockIdx.y;
    const float4* s0 = (const float4*)(wi0 + (long long)z * DMODEL * FDIM);
    const float4* s1 = (const float4*)(wi1 + (long long)z * DMODEL * FDIM);
    float4 a = s0[i], b = s1[i];
    uint32_t* w = (uint32_t*)(dst + (long long)z * DMODEL * 2 * FDIM + i * 8);
    w[0] = packh2(__float2half(a.x), __float2half(b.x));
    w[1] = packh2(__float2half(a.y), __float2half(b.y));
    w[2] = packh2(__float2half(a.z), __float2half(b.z));
    w[3] = packh2(__float2half(a.w), __float2half(b.w));
}

// ---------------- RMSNorm (+optional fp32 out, fp16 out) ----------------
__global__ void rmsnorm_split_k(const float* __restrict__ x, const float* __restrict__ sc,
                                float* __restrict__ yf, fp16* __restrict__ yh)
{
    int row = blockIdx.x;
    int tid = threadIdx.x;
    const float* xr = x + (size_t)row * DMODEL;
    float ss = 0.f;
    for (int d = tid; d < DMODEL; d += 256) { float v = xr[d]; ss += v * v; }
    __shared__ float red[256];
    red[tid] = ss; __syncthreads();
    for (int st = 128; st > 0; st >>= 1) {
        if (tid < st) red[tid] += red[tid + st];
        __syncthreads();
    }
    float inv = rsqrtf(red[0] / (float)DMODEL + 1e-6f);
    size_t base = (size_t)row * DMODEL;
    for (int d = tid; d < DMODEL; d += 256) {
        float v = xr[d] * inv * sc[d];
        if (yf) yf[base + d] = v;
        yh[base + d] = __float2half(v);
    }
}

// ================= fp16 tensor-core GEMM (128x128, occ 2, 3-stage) ==========
#define ASTR 40
#define BSTR 136
#define OFF_A(s) ((s)*5120)
#define OFF_B(s) (15360 + (s)*4352)
#define SMEM_GEMM_BYTES (28416*2)

__global__ __launch_bounds__(256, 2)
void fp16_gemm_k(const fp16* __restrict__ Ag, const fp16* __restrict__ Bg,
                 const float* __restrict__ res, float* __restrict__ Cf,
                 fp16* __restrict__ SH,
                 int M, int N, int K,
                 const int* __restrict__ perm,
                 const int* __restrict__ cnts, const int* __restrict__ offs,
                 long long strideB, int mode)
{
    extern __shared__ fp16 sm[];
    int rowBase = 0;
    const fp16* B = Bg;
    if (cnts) {
        int e = blockIdx.z;
        M = cnts[e];
        rowBase = offs[e];
        B = Bg + (long long)e * strideB;
    }
    int bm = blockIdx.y * 128;
    if (bm >= M) return;
    int bn = blockIdx.x * 128;

    int tid  = threadIdx.x;
    int lane = tid & 31;
    int w    = tid >> 5;
    int wm   = w & 1;
    int wn   = w >> 1;

    uint32_t smBase = (uint32_t)__cvta_generic_to_shared(sm);
    uint32_t aLane  = ((lane & 15) * ASTR + (lane >> 4) * 8) * 2;
    uint32_t bLane  = ((lane & 15) * BSTR) * 2;

    int rA  = tid >> 1;
    int ac0 = (tid & 1) * 16;
    int aIdx = -1;
    if (bm + rA < M) { int r = rowBase + bm + rA; aIdx = perm ? perm[r] : r; }

    int rB  = tid >> 3;
    int bc0 = (tid & 7) * 8;

    float acc[4][4][4];
#pragma unroll
    for (int i = 0; i < 4; i++)
#pragma unroll
        for (int j = 0; j < 4; j++)
#pragma unroll
            for (int c = 0; c < 4; c++) acc[i][j][c] = 0.f;

    const int NKT = K >> 5;

    auto prefetch = [&](int kt, int st) {
        int k0 = kt << 5;
        uint32_t dA = smBase + (OFF_A(st) + rA * ASTR + ac0) * 2;
        if (aIdx >= 0) {
            const fp16* sa = Ag + (size_t)aIdx * K + k0 + ac0;
            cp16(dA, sa);      cp16(dA + 16, sa + 8);
        } else {
            cp16_zero(dA, Ag); cp16_zero(dA + 16, Ag);
        }
        uint32_t dB = smBase + (OFF_B(st) + rB * BSTR + bc0) * 2;
        const fp16* sb = B + (size_t)(k0 + rB) * N + bn + bc0;
        cp16(dB, sb);       cp16(dB + 128, sb + 64);
    };

    prefetch(0, 0); CP_COMMIT();
    prefetch(1, 1); CP_COMMIT();

    for (int kt = 0; kt < NKT; kt++) {
        int st = kt % 3;
        if (kt + 1 < NKT) asm volatile("cp.async.wait_group 1;" ::: "memory");
        else              asm volatile("cp.async.wait_group 0;" ::: "memory");
        __syncthreads();

        uint32_t aBase = smBase + (OFF_A(st) + wm * 64 * ASTR) * 2 + aLane;
        uint32_t bBase = smBase + (OFF_B(st)) * 2 + wn * 32 * 2 + bLane;

#pragma unroll
        for (int ks = 0; ks < 2; ks++) {
            uint32_t ah[4][4];
#pragma unroll
            for (int mf = 0; mf < 4; mf++) {
                uint32_t off = mf * (16 * ASTR * 2) + ks * 32;
                ldm_x4(ah[mf], aBase + off);
            }
            uint32_t bh[4][2];
#pragma unroll
            for (int nf = 0; nf < 4; nf++) {
                uint32_t off = nf * 16 + ks * (16 * BSTR * 2);
                ldm_x2t(bh[nf], bBase + off);
            }
#pragma unroll
            for (int mf = 0; mf < 4; mf++)
#pragma unroll
                for (int nf = 0; nf < 4; nf++)
                    mma_f16(acc[mf][nf], ah[mf], bh[nf]);
        }

        if (kt + 2 < NKT) {
            prefetch(kt + 2, (kt + 2) % 3);
            CP_COMMIT();
        }
    }

    int g   = lane >> 2;
    int tig = lane & 3;
#pragma unroll
    for (int mf = 0; mf < 4; mf++) {
        int row0 = bm + wm * 64 + mf * 16 + g;
        int row1 = row0 + 8;
#pragma unroll
        for (int nf = 0; nf < 4; nf++) {
            int col = bn + wn * 32 + nf * 8 + tig * 2;
            if (mode == 0) {
                if (row0 < M) {
                    size_t o = (size_t)(rowBase + row0) * N + col;
                    float2 v = make_float2(acc[mf][nf][0], acc[mf][nf][1]);
                    if (res) { float2 r = *(const float2*)&res[o]; v.x += r.x; v.y += r.y; }
                    *(float2*)&Cf[o] = v;
                }
                if (row1 < M) {
                    size_t o = (size_t)(rowBase + row1) * N + col;
                    float2 v = make_float2(acc[mf][nf][2], acc[mf][nf][3]);
                    if (res) { float2 r = *(const float2*)&res[o]; v.x += r.x; v.y += r.y; }
                    *(float2*)&Cf[o] = v;
                }
            } else if (mode == 1) {
                // interleaved silu: even col = gate (wi0), odd col = value (wi1)
                int f = col >> 1;
                if (row0 < M) {
                    size_t o = (size_t)(rowBase + row0) * (size_t)(N >> 1) + f;
                    float a = acc[mf][nf][0], b = acc[mf][nf][1];
                    SH[o] = __float2half((a / (1.0f + __expf(-a))) * b);
                }
                if (row1 < M) {
                    size_t o = (size_t)(rowBase + row1) * (size_t)(N >> 1) + f;
                    float a = acc[mf][nf][2], b = acc[mf][nf][3];
                    SH[o] = __float2half((a / (1.0f + __expf(-a))) * b);
                }
            } else {
                // mode 2: plain fp16 output
                if (row0 < M) {
                    size_t o = (size_t)(rowBase + row0) * N + col;
                    *(uint32_t*)&SH[o] = packh2(__float2half(acc[mf][nf][0]),
                                                __float2half(acc[mf][nf][1]));
                }
                if (row1 < M) {
                    size_t o = (size_t)(rowBase + row1) * N + col;
                    *(uint32_t*)&SH[o] = packh2(__float2half(acc[mf][nf][2]),
                                                __float2half(acc[mf][nf][3]));
                }
            }
        }
    }
}

// ---------------- RoPE in-place on fp16 qkv buffer ----------------
__global__ void rope16_k(fp16* __restrict__ qkv, const int* __restrict__ pos,
                         int srcOff, int nheads, float scale, int total)
{
    int idx = blockIdx.x * blockDim.x + threadIdx.x;
    if (idx >= total) return;
    int i   = idx & 63;
    int th  = idx >> 6;
    int h   = th % nheads;
    int tok = th / nheads;
    float freq = powf(10000.0f, -(float)i / 64.0f);
    float ang = (float)pos[tok] * freq;
    float c = cosf(ang), s = sinf(ang);
    fp16* row = qkv + (size_t)tok * QKVN + srcOff + h * HD;
    float x1 = __half2float(row[i]), x2 = __half2float(row[i + 64]);
    row[i]      = __float2half((x1 * c - x2 * s) * scale);
    row[i + 64] = __float2half((x2 * c + x1 * s) * scale);
}

// ================= fp16 flash attention (strided qkv16 input) =================
#define FQT 64
#define FKT 32
#define FSTR 136
#define F_Q 0
#define F_K(s) (8704 + (s)*4352)
#define F_V(s) (17408 + (s)*4352)
#define FLASH_SMEM_BYTES (26112*2)

__global__ __launch_bounds__(128)
void flash2_k(const fp16* __restrict__ qkv16,
              const int* __restrict__ seg, fp16* __restrict__ Oh)
{
    extern __shared__ fp16 fsm[];
    __shared__ int Sq[FQT];
    __shared__ int Sk[2][FKT];

    int tid  = threadIdx.x;
    int lane = tid & 31;
    int w    = tid >> 5;
    int g    = lane >> 2;
    int tig  = lane & 3;

    int q0  = blockIdx.x * FQT;
    int h   = blockIdx.y;
    int b   = blockIdx.z;
    int tok0 = b * S_LEN;
    int hk  = h >> 1;

    uint32_t smBase = (uint32_t)__cvta_generic_to_shared(fsm);

    {
        int r  = tid >> 1;
        int c0 = (tid & 1) * 64;
        const fp16* sq = qkv16 + (size_t)(tok0 + q0 + r) * QKVN + h * HD + c0;
        uint32_t dq = smBase + (F_Q + r * FSTR + c0) * 2;
#pragma unroll
        for (int j = 0; j < 8; j++) cp16(dq + j * 16, sq + j * 8);
    }
    if (tid < FQT) Sq[tid] = seg[tok0 + q0 + tid];

    auto prefetch = [&](int kt, int st) {
        int k0 = kt * FKT;
        int r  = tid >> 2;
        int c0 = (tid & 3) * 32;
        const fp16* base = qkv16 + (size_t)(tok0 + k0 + r) * QKVN + hk * HD + c0;
        uint32_t dk = smBase + (F_K(st) + r * FSTR + c0) * 2;
        uint32_t dv = smBase + (F_V(st) + r * FSTR + c0) * 2;
#pragma unroll
        for (int j = 0; j < 4; j++) {
            cp16(dk + j * 16, base + 2048 + j * 8);
            cp16(dv + j * 16, base + 3072 + j * 8);
        }
        if (tid < FKT) Sk[st][tid] = seg[tok0 + k0 + tid];
    };

    prefetch(0, 0);
    CP_COMMIT();

    float of[16][4];
#pragma unroll
    for (int nf = 0; nf < 16; nf++)
#pragma unroll
        for (int c = 0; c < 4; c++) of[nf][c] = 0.f;
    float m0 = -1e9f, m1 = -1e9f, l0 = 0.f, l1 = 0.f;

    uint32_t qAddr = smBase + (F_Q + (w * 16 + (lane & 15)) * FSTR + (lane >> 4) * 8) * 2;
    int ktokoff = (lane & 7) + ((lane >> 4) << 3);
    int kdhalf  = ((lane >> 3) & 1) * 8;
    int vrow    = lane & 15;

    int ktend = (q0 + FQT - 1) / FKT;
    int myrow0 = q0 + w * 16 + g;
    int myrow1 = myrow0 + 8;
    int sq0 = 0, sq1 = 0;

    for (int kt = 0; kt <= ktend; kt++) {
        int st = kt & 1;
        if (kt + 1 <= ktend) {
            prefetch(kt + 1, st ^ 1);
            CP_COMMIT();
            asm volatile("cp.async.wait_group 1;" ::: "memory");
        } else {
            asm volatile("cp.async.wait_group 0;" ::: "memory");
        }
        __syncthreads();
        if (kt == 0) { sq0 = Sq[w * 16 + g]; sq1 = Sq[w * 16 + g + 8]; }
        int k0 = kt * FKT;

        float sf[4][4];
#pragma unroll
        for (int nf = 0; nf < 4; nf++)
#pragma unroll
            for (int c = 0; c < 4; c++) sf[nf][c] = 0.f;

        uint32_t kBase = smBase + (F_K(st) + ktokoff * FSTR + kdhalf) * 2;

#pragma unroll
        for (int kk = 0; kk < 8; kk++) {
            uint32_t qh4[4];
            ldm_x4(qh4, qAddr + kk * 32);
#pragma unroll
            for (int p = 0; p < 2; p++) {
                uint32_t kh4[4];
                uint32_t off = (p * 16 * FSTR + kk * 16) * 2;
                ldm_x4(kh4, kBase + off);
                mma_f16(sf[2 * p],     qh4, kh4);
                mma_f16(sf[2 * p + 1], qh4, kh4 + 2);
            }
        }

#pragma unroll
        for (int nf = 0; nf < 4; nf++) {
            int c0g = k0 + nf * 8 + 2 * tig;
            int sk0 = Sk[st][nf * 8 + 2 * tig];
            int sk1 = Sk[st][nf * 8 + 2 * tig + 1];
            if (c0g > myrow0     || sk0 != sq0) sf[nf][0] = -1e9f;
            if (c0g + 1 > myrow0 || sk1 != sq0) sf[nf][1] = -1e9f;
            if (c0g > myrow1     || sk0 != sq1) sf[nf][2] = -1e9f;
            if (c0g + 1 > myrow1 || sk1 != sq1) sf[nf][3] = -1e9f;
        }
        float mx0 = -1e9f, mx1 = -1e9f;
#pragma unroll
        for (int nf = 0; nf < 4; nf++) {
            mx0 = fmaxf(mx0, fmaxf(sf[nf][0], sf[nf][1]));
            mx1 = fmaxf(mx1, fmaxf(sf[nf][2], sf[nf][3]));
        }
        mx0 = fmaxf(mx0, __shfl_xor_sync(0xffffffff, mx0, 1));
        mx0 = fmaxf(mx0, __shfl_xor_sync(0xffffffff, mx0, 2));
        mx1 = fmaxf(mx1, __shfl_xor_sync(0xffffffff, mx1, 1));
        mx1 = fmaxf(mx1, __shfl_xor_sync(0xffffffff, mx1, 2));
        float mn0 = fmaxf(m0, mx0), mn1 = fmaxf(m1, mx1);
        float al0 = __expf(m0 - mn0), al1 = __expf(m1 - mn1);
        m0 = mn0; m1 = mn1;
        float ls0 = 0.f, ls1 = 0.f;
#pragma unroll
        for (int nf = 0; nf < 4; nf++) {
            sf[nf][0] = __expf(sf[nf][0] - mn0);
            sf[nf][1] = __expf(sf[nf][1] - mn0);
            sf[nf][2] = __expf(sf[nf][2] - mn1);
            sf[nf][3] = __expf(sf[nf][3] - mn1);
            ls0 += sf[nf][0] + sf[nf][1];
            ls1 += sf[nf][2] + sf[nf][3];
        }
        l0 = l0 * al0 + ls0;
        l1 = l1 * al1 + ls1;
#pragma unroll
        for (int nf = 0; nf < 16; nf++) {
            of[nf][0] *= al0; of[nf][1] *= al0;
            of[nf][2] *= al1; of[nf][3] *= al1;
        }

        uint32_t vBase = smBase + (F_V(st) + vrow * FSTR) * 2;
#pragma unroll
        for (int t = 0; t < 2; t++) {
            uint32_t pah[4];
#pragma unroll
            for (int q = 0; q < 2; q++) {
                pah[2 * q]     = packh2(__float2half(sf[2 * t + q][0]),
                                        __float2half(sf[2 * t + q][1]));
                pah[2 * q + 1] = packh2(__float2half(sf[2 * t + q][2]),
                                        __float2half(sf[2 * t + q][3]));
            }
#pragma unroll
            for (int nf = 0; nf < 16; nf++) {
                uint32_t vh2[2];
                uint32_t off = (t * 16 * FSTR + nf * 8) * 2;
                ldm_x2t(vh2, vBase + off);
                mma_f16(of[nf], pah, vh2);
            }
        }
        __syncthreads();
    }

    l0 += __shfl_xor_sync(0xffffffff, l0, 1);
    l0 += __shfl_xor_sync(0xffffffff, l0, 2);
    l1 += __shfl_xor_sync(0xffffffff, l1, 1);
    l1 += __shfl_xor_sync(0xffffffff, l1, 2);
    float i0 = 1.0f / l0, i1 = 1.0f / l1;
    size_t r0 = (size_t)(tok0 + myrow0) * DMODEL + h * HD;
    size_t r1 = (size_t)(tok0 + myrow1) * DMODEL + h * HD;
#pragma unroll
    for (int nf = 0; nf < 16; nf++) {
        int col = nf * 8 + 2 * tig;
        *(uint32_t*)&Oh[r0 + col] = packh2(__float2half(of[nf][0] * i0),
                                           __float2half(of[nf][1] * i0));
        *(uint32_t*)&Oh[r1 + col] = packh2(__float2half(of[nf][2] * i1),
                                           __float2half(of[nf][3] * i1));
    }
}

// ---------------- gating ----------------
__global__ void gate_k(const float* __restrict__ h, const float* __restrict__ gw,
                       int* __restrict__ tope, float* __restrict__ wgt)
{
    int tok = blockIdx.x;
    int tid = threadIdx.x;
    float s[NEXP];
#pragma unroll
    for (int e = 0; e < NEXP; e++) s[e] = 0.f;
    const float* hr = h + (size_t)tok * DMODEL;
    for (int d = tid; d < DMODEL; d += 128) {
        float hv = hr[d];
#pragma unroll
        for (int e = 0; e < NEXP; e++) s[e] += hv * gw[d * NEXP + e];
    }
    __shared__ float red[NEXP][128];
#pragma unroll
    for (int e = 0; e < NEXP; e++) red[e][tid] = s[e];
    __syncthreads();
    for (int st = 64; st > 0; st >>= 1) {
        if (tid < st)
#pragma unroll
            for (int e = 0; e < NEXP; e++) red[e][tid] += red[e][tid + st];
        __syncthreads();
    }
    if (tid == 0) {
        float l[NEXP];
#pragma unroll
        for (int e = 0; e < NEXP; e++) l[e] = red[e][0];
        int i0 = 0;
#pragma unroll
        for (int e = 1; e < NEXP; e++) if (l[e] > l[i0]) i0 = e;
        int i1 = -1;
#pragma unroll
        for (int e = 0; e < NEXP; e++)
            if (e != i0 && (i1 < 0 || l[e] > l[i1])) i1 = e;
        float z = expf(l[i1] - l[i0]);
        float w0 = 1.0f / (1.0f + z);
        tope[tok * 2]     = i0;  wgt[tok * 2]     = w0;
        tope[tok * 2 + 1] = i1;  wgt[tok * 2 + 1] = 1.0f - w0;
    }
}

// ---------------- bucketize ----------------
__global__ void bucketize_k()
{
    __shared__ int sc[NEXP], cur[NEXP];
    int tid = threadIdx.x;
    if (tid < NEXP) sc[tid] = 0;
    __syncthreads();
    for (int a = tid; a < NASSIGN; a += 256) atomicAdd(&sc[g_tope[a]], 1);
    __syncthreads();
    if (tid == 0) {
        int o = 0;
        for (int e = 0; e < NEXP; e++) {
            g_cnt[e] = sc[e]; g_off[e] = o; cur[e] = o; o += sc[e];
        }
    }
    __syncthreads();
    for (int a = tid; a < NASSIGN; a += 256) {
        int e = g_tope[a];
        int p = atomicAdd(&cur[e], 1);
        g_perm[p] = a >> 1;
        g_slot[a] = p;
    }
}

// ---------------- combine (vectorized float4) ----------------
__global__ void combine_k(float* __restrict__ out, int total4)
{
    int idx = blockIdx.x * blockDim.x + threadIdx.x;
    if (idx >= total4) return;
    int e   = idx * 4;
    int tok = e >> 11;
    int d   = e & 2047;
    int s0 = g_slot[tok * 2],     s1 = g_slot[tok * 2 + 1];
    float w0 = g_wgt[tok * 2],    w1 = g_wgt[tok * 2 + 1];
    float4 a = *(const float4*)&g_inter[e];
    float4 b = *(const float4*)&g_eout[(size_t)s0 * DMODEL + d];
    float4 c = *(const float4*)&g_eout[(size_t)s1 * DMODEL + d];
    float4 r;
    r.x = a.x + w0 * b.x + w1 * c.x;
    r.y = a.y + w0 * b.y + w1 * c.y;
    r.z = a.z + w0 * b.z + w1 * c.z;
    r.w = a.w + w0 * b.w + w1 * c.w;
    *(float4*)&out[e] = r;
}

// =============================== launcher ===============================
extern "C" void kernel_launch(void* const* d_in, const int* in_sizes, int n_in,
                              void* d_out, int out_size)
{
    const float* inputs  = (const float*)d_in[0];
    const float* pre_s   = (const float*)d_in[1];
    const float* post_s  = (const float*)d_in[2];
    const float* wq      = (const float*)d_in[3];
    const float* wk      = (const float*)d_in[4];
    const float* wv      = (const float*)d_in[5];
    const float* wo_attn = (const float*)d_in[6];
    const float* gate_w  = (const float*)d_in[7];
    const float* wi0     = (const float*)d_in[8];
    const float* wi1     = (const float*)d_in[9];
    const float* wo_mlp  = (const float*)d_in[10];
    const int*   seg     = (const int*)d_in[11];
    const int*   pos     = (const int*)d_in[12];
    float* out = (float*)d_out;

    float *inter, *h, *eout, *wgt;
    int *perm, *slot, *tope, *cnt, *off;
    fp16 *qkv16,*lnx,*ctx,*hh,*act,*qkvw,*wo,*w01,*wom;
    cudaGetSymbolAddress((void**)&inter,g_inter);
    cudaGetSymbolAddress((void**)&h,    g_hbuf);
    cudaGetSymbolAddress((void**)&eout, g_eout);
    cudaGetSymbolAddress((void**)&perm, g_perm);
    cudaGetSymbolAddress((void**)&slot, g_slot);
    cudaGetSymbolAddress((void**)&tope, g_tope);
    cudaGetSymbolAddress((void**)&wgt,  g_wgt);
    cudaGetSymbolAddress((void**)&cnt,  g_cnt);
    cudaGetSymbolAddress((void**)&off,  g_off);
    cudaGetSymbolAddress((void**)&qkv16,g_qkv16);
    cudaGetSymbolAddress((void**)&lnx,  g_lnx);
    cudaGetSymbolAddress((void**)&ctx,  g_ctx);
    cudaGetSymbolAddress((void**)&hh,   g_hh);
    cudaGetSymbolAddress((void**)&act,  g_act);
    cudaGetSymbolAddress((void**)&qkvw, g_qkvw);
    cudaGetSymbolAddress((void**)&wo,   g_wo);
    cudaGetSymbolAddress((void**)&w01,  g_w01);
    cudaGetSymbolAddress((void**)&wom,  g_wom);

    cudaFuncSetAttribute(fp16_gemm_k, cudaFuncAttributeMaxDynamicSharedMemorySize,
                         SMEM_GEMM_BYTES);
    cudaFuncSetAttribute(flash2_k, cudaFuncAttributeMaxDynamicSharedMemorySize,
                         FLASH_SMEM_BYTES);

    // 0) weight converts (fp16, vectorized)
    {
        long long t4;
        t4 = (long long)DMODEL * DMODEL / 4;
        wcvt4_k<<<dim3((unsigned)((t4 + 255) / 256), 1), 256>>>(
            wq, qkvw, DMODEL, QKVN, 0, 0, 0, t4);
        t4 = (long long)DMODEL * (HKVN * HD) / 4;
        wcvt4_k<<<dim3((unsigned)((t4 + 255) / 256), 1), 256>>>(
            wk, qkvw, HKVN * HD, QKVN, 2048, 0, 0, t4);
        wcvt4_k<<<dim3((unsigned)((t4 + 255) / 256), 1), 256>>>(
            wv, qkvw, HKVN * HD, QKVN, 3072, 0, 0, t4);
        t4 = (long long)DMODEL * DMODEL / 4;
        wcvt4_k<<<dim3((unsigned)((t4 + 255) / 256), 1), 256>>>(
            wo_attn, wo, DMODEL, DMODEL, 0, 0, 0, t4);
        t4 = (long long)DMODEL * FDIM / 4;
        w01cvt_k<<<dim3((unsigned)((t4 + 255) / 256), NEXP), 256>>>(wi0, wi1, w01, t4);
        t4 = (long long)FDIM * DMODEL / 4;
        wcvt4_k<<<dim3((unsigned)((t4 + 255) / 256), NEXP), 256>>>(
            wo_mlp, wom, DMODEL, DMODEL, 0,
            (long long)FDIM * DMODEL, (long long)FDIM * DMODEL, t4);
    }

    // 1) pre-attention RMSNorm -> lnx fp16
    rmsnorm_split_k<<<NT, 256>>>(inputs, pre_s, nullptr, lnx);

    // 2) fused QKV projection -> qkv16 (fp16, mode 2)
    fp16_gemm_k<<<dim3(QKVN/128, NT/128, 1), 256, SMEM_GEMM_BYTES>>>(
        lnx, qkvw, nullptr, nullptr, qkv16,
        NT, QKVN, DMODEL, nullptr, nullptr, nullptr, 0, 2);

    // 3) RoPE in place (q scaled, k unscaled); v untouched
    {
        int totq = NT * HQN * 64;
        rope16_k<<<(totq + 255) / 256, 256>>>(qkv16, pos, 0, HQN,
            0.08838834764831845f, totq);
        int totk = NT * HKVN * 64;
        rope16_k<<<(totk + 255) / 256, 256>>>(qkv16, pos, 2048, HKVN, 1.0f, totk);
    }

    // 4) flash attention (strided reads) -> ctx fp16
    flash2_k<<<dim3(S_LEN/FQT, HQN, BATCH), 128, FLASH_SMEM_BYTES>>>(
        qkv16, seg, ctx);

    // 5) O projection + residual -> inter
    fp16_gemm_k<<<dim3(DMODEL/128, NT/128, 1), 256, SMEM_GEMM_BYTES>>>(
        ctx, wo, inputs, inter, nullptr,
        NT, DMODEL, DMODEL, nullptr, nullptr, nullptr, 0, 0);

    // 6) post-attention RMSNorm -> h fp32 + fp16
    rmsnorm_split_k<<<NT, 256>>>(inter, post_s, h, hh);

    // 7) gating
    gate_k<<<NT, 128>>>(h, gate_w, tope, wgt);

    // 8) bucketize
    bucketize_k<<<1, 256>>>();

    // 9) fused MoE up-projection + SiLU (interleaved wi0/wi1) -> act fp16
    fp16_gemm_k<<<dim3((2*FDIM)/128, NASSIGN/128, NEXP), 256, SMEM_GEMM_BYTES>>>(
        hh, w01, nullptr, nullptr, act,
        0, 2*FDIM, DMODEL, perm, cnt, off, (long long)DMODEL * 2 * FDIM, 1);

    // 10) MoE down-projection -> eout
    fp16_gemm_k<<<dim3(DMODEL/128, NASSIGN/128, NEXP), 256, SMEM_GEMM_BYTES>>>(
        act, wom, nullptr, eout, nullptr,
        0, DMODEL, FDIM, nullptr, cnt, off, (long long)FDIM * DMODEL, 0);

    // 11) combine
    combine_k<<<(NT * DMODEL / 4 + 255) / 256, 256>>>(out, NT * DMODEL / 4);
}